// round 11
// baseline (speedup 1.0000x reference)
#include <cuda_runtime.h>
#include <cuda_fp16.h>
#include <cstdint>

#define EPSF 1e-9f
typedef unsigned long long u64;
typedef unsigned int u32;

// ---------------- persistent device scratch ----------------
__device__ __half g_h1h[256*400*256];          // conv1 out NHWC fp16  52MB
__device__ __half g_wh[256*20736];             // caps1 W [co][tap*256+ci] fp16
__device__ float g_h2[256*256*36];             // caps1 out (relu'd)  [b][co][36]
__device__ float g_u[256u*1152*10*16];         // prediction vectors  189MB
__device__ float g_blog[256*11520];            // routing logits
__device__ float g_masked[256*16];
__device__ float g_fc1[256*512];
__device__ float g_fc2[256*1024];

// ---------------- helpers ----------------
__device__ __forceinline__ void fma2(u64& acc, u64 a, u64 b) {
    asm("fma.rn.f32x2 %0, %1, %2, %0;" : "+l"(acc) : "l"(a), "l"(b));
}
__device__ __forceinline__ u64 pack2(float lo, float hi) {
    u64 r; unsigned il = __float_as_uint(lo), ih = __float_as_uint(hi);
    asm("mov.b64 %0, {%1, %2};" : "=l"(r) : "r"(il), "r"(ih));
    return r;
}
__device__ __forceinline__ u64 pack_dup(float v) {
    u64 r; unsigned iv = __float_as_uint(v);
    asm("mov.b64 %0, {%1, %1};" : "=l"(r) : "r"(iv));
    return r;
}
__device__ __forceinline__ void unpack2(u64 v, float& lo, float& hi) {
    asm("mov.b64 {%0, %1}, %2;" : "=f"(lo), "=f"(hi) : "l"(v));
}
__device__ __forceinline__ u32 smem_u32(const void* p) {
    u32 a;
    asm("{ .reg .u64 t; cvta.to.shared.u64 t, %1; cvt.u32.u64 %0, t; }" : "=r"(a) : "l"(p));
    return a;
}
__device__ __forceinline__ void cp16(u32 dst, const void* src) {
    asm volatile("cp.async.cg.shared.global [%0], [%1], 16;" :: "r"(dst), "l"(src) : "memory");
}
__device__ __forceinline__ void cp_commit() { asm volatile("cp.async.commit_group;" ::: "memory"); }
#define CP_WAIT(n) asm volatile("cp.async.wait_group %0;" :: "n"(n) : "memory")

// fp16 warp MMA m16n8k16, fp32 accum
#define MMAF16(c, a, b0, b1) \
    asm volatile("mma.sync.aligned.m16n8k16.row.col.f32.f16.f16.f32 " \
        "{%0,%1,%2,%3}, {%4,%5,%6,%7}, {%8,%9}, {%0,%1,%2,%3};" \
        : "+f"((c)[0]), "+f"((c)[1]), "+f"((c)[2]), "+f"((c)[3]) \
        : "r"((a)[0]), "r"((a)[1]), "r"((a)[2]), "r"((a)[3]), "r"(b0), "r"(b1))

// ---------------- weight prep: w[co][ci][9][9] fp32 -> g_wh[co][tap*256+ci] fp16 ----------------
__global__ void prep_w_kernel(const float* __restrict__ w) {
    int k  = blockIdx.x * 256 + threadIdx.x;   // 0..20735 (grid.x = 81)
    int co = blockIdx.y;
    int tap = k >> 8, ci = k & 255;
    g_wh[(size_t)co * 20736 + k] = __float2half(w[(size_t)co * 20736 + ci * 81 + tap]);
}

// ---------------- conv1: (B,1,28,28) -> relu -> NHWC fp16 (B,20,20,256) ----------------
__global__ __launch_bounds__(256)
void conv1_kernel(const float* __restrict__ x, const float* __restrict__ w,
                  const float* __restrict__ bias) {
    __shared__ float img[784];
    __shared__ float ws[2592];                 // layout [tap][32 co]
    int b = blockIdx.y, co0 = blockIdx.x * 32;
    int tid = threadIdx.x;
    for (int i = tid; i < 784; i += 256) img[i] = x[b * 784 + i];
    for (int i = tid; i < 2592; i += 256) {
        int t = i >> 5, c = i & 31;
        ws[i] = w[(co0 + c) * 81 + t];
    }
    u64 b2[16];
    #pragma unroll
    for (int c = 0; c < 16; c++) b2[c] = pack2(bias[co0 + 2*c], bias[co0 + 2*c + 1]);
    __syncthreads();

    for (int p = tid; p < 400; p += 256) {
        int oy = p / 20, ox = p % 20;
        u64 acc[16];
        #pragma unroll
        for (int c = 0; c < 16; c++) acc[c] = b2[c];
        #pragma unroll 1
        for (int dy = 0; dy < 9; dy++) {
            const float* row = img + (oy + dy) * 28 + ox;
            u64 rr[9];
            #pragma unroll
            for (int dx = 0; dx < 9; dx++) rr[dx] = pack_dup(row[dx]);
            #pragma unroll
            for (int dx = 0; dx < 9; dx++) {
                const u64* wp = (const u64*)(ws + (dy * 9 + dx) * 32);
                #pragma unroll
                for (int c = 0; c < 16; c++) fma2(acc[c], wp[c], rr[dx]);
            }
        }
        size_t base = ((size_t)b * 400 + p) * 256 + co0;
        #pragma unroll
        for (int c = 0; c < 16; c++) {
            float lo, hi; unpack2(acc[c], lo, hi);
            *reinterpret_cast<__half2*>(&g_h1h[base + 2*c]) =
                __halves2half2(__float2half(fmaxf(lo, 0.f)), __float2half(fmaxf(hi, 0.f)));
        }
    }
}

// ---------------- caps1 via mma.sync fp16: C[9216,256] = A[9216,20736] @ W^T ----------------
// 256 threads (8 warps 4x2), CTA tile M=128 x N=128, grid 144 (~1 CTA/SM).
// K-step 16, 1296 steps, 3-stage cp.async pipeline.
// stage: A 128x48B = 6K | B 128x48B = 6K -> 12KB; 3 stages = 36KB.
static constexpr int CSTG = 12288;
static constexpr u32 SMEM_C1 = 3 * CSTG;   // 36864 < 48KB default

__global__ __launch_bounds__(256, 1)
void caps1_mma_kernel(const float* __restrict__ bias) {
    extern __shared__ char smem[];
    u32 sm = smem_u32(smem);
    int tid = threadIdx.x;
    int n0 = blockIdx.x * 128, m0 = blockIdx.y * 128;

    // loader: rw = tid>>1 (0..127), ch = tid&1 (16B chunk = 8 fp16); 2 cp16/thread/step
    int rw = tid >> 1, ch = tid & 1;
    int pl = m0 + rw;
    int pb = pl / 36, prr = pl % 36, loy = prr / 6, lox = prr % 6;
    u32 aPix = (u32)((pb * 20 + 2 * loy) * 20 + 2 * lox) * 256 + ch * 8;
    u32 bRow = (u32)(n0 + rw) * 20736 + ch * 8;
    u32 rowOff = (u32)(rw * 48 + ch * 16);

    auto load_stage = [&](int s, int step) {
        u32 base = sm + s * CSTG;
        int tap = step >> 4, ci0 = (step & 15) * 16;
        int dy = tap / 9, dx = tap - dy * 9;
        u32 asrc = aPix + (u32)(dy * 20 + dx) * 256 + ci0;
        u32 bs = (u32)tap * 256 + ci0;
        cp16(base + rowOff,        g_h1h + asrc);
        cp16(base + 6144 + rowOff, g_wh + bRow + bs);
        cp_commit();
    };

    int wid = tid >> 5, lane = tid & 31;
    int wm = wid & 3, wn = wid >> 2;               // warp tile: M 32, N 64
    int g = lane >> 2, tc = lane & 3;

    float c[2][8][4];
    #pragma unroll
    for (int i = 0; i < 2; i++)
        #pragma unroll
        for (int j = 0; j < 8; j++)
            #pragma unroll
            for (int q = 0; q < 4; q++) c[i][j][q] = 0.f;

    load_stage(0, 0);
    load_stage(1, 1);

    #pragma unroll 1
    for (int step = 0; step < 1296; step++) {
        int cur = step % 3;
        if (step + 1 < 1296) { CP_WAIT(1); } else { CP_WAIT(0); }
        __syncthreads();                       // stage cur ready; stage (cur+2)%3 free
        if (step + 2 < 1296) load_stage((step + 2) % 3, step + 2);

        const u32* Ah = (const u32*)(smem + cur * CSTG);
        const u32* Bh = Ah + 1536;     // +6144B
        u32 ah[2][4];
        #pragma unroll
        for (int tm = 0; tm < 2; tm++) {
            int r = wm * 32 + tm * 16 + g;
            ah[tm][0] = Ah[r * 12 + tc];       ah[tm][1] = Ah[(r + 8) * 12 + tc];
            ah[tm][2] = Ah[r * 12 + tc + 4];   ah[tm][3] = Ah[(r + 8) * 12 + tc + 4];
        }
        #pragma unroll
        for (int tn = 0; tn < 8; tn++) {
            int n = wn * 64 + tn * 8 + g;
            u32 bh0 = Bh[n * 12 + tc], bh1 = Bh[n * 12 + tc + 4];
            #pragma unroll
            for (int tm = 0; tm < 2; tm++)
                MMAF16(c[tm][tn], ah[tm], bh0, bh1);
        }
    }
    __syncthreads();

    // epilogue: bias + relu -> g_h2[b][co][36]
    #pragma unroll
    for (int tm = 0; tm < 2; tm++) {
        int r0 = m0 + wm * 32 + tm * 16 + g;
        int b0i = r0 / 36, rr0 = r0 % 36;
        int r1 = r0 + 8;
        int b1i = r1 / 36, rr1 = r1 % 36;
        float* d0 = g_h2 + (size_t)b0i * 9216 + rr0;
        float* d1 = g_h2 + (size_t)b1i * 9216 + rr1;
        #pragma unroll
        for (int tn = 0; tn < 8; tn++) {
            int cc = n0 + wn * 64 + tn * 8 + tc * 2;
            float bv0 = bias[cc], bv1 = bias[cc + 1];
            d0[(size_t)cc * 36]       = fmaxf(c[tm][tn][0] + bv0, 0.f);
            d0[(size_t)(cc + 1) * 36] = fmaxf(c[tm][tn][1] + bv1, 0.f);
            d1[(size_t)cc * 36]       = fmaxf(c[tm][tn][2] + bv0, 0.f);
            d1[(size_t)(cc + 1) * 36] = fmaxf(c[tm][tn][3] + bv1, 0.f);
        }
    }
}

// ---------------- u = Wj @ x_tile: warp-per-W-row, persistent over batches ----------------
// 1440 blocks x 8 warps; warp owns row r (W row in regs, read ONCE), loops b=0..255.
// x: 2 broadcast float4 L2 loads per (warp, b); writes 64B coalesced per warp-iter.
__global__ __launch_bounds__(256)
void u_kernel(const float* __restrict__ W) {
    int tid = threadIdx.x, wid = tid >> 5, lane = tid & 31;
    int r = blockIdx.x * 8 + wid;
    float4 w4 = reinterpret_cast<const float4*>(W)[(size_t)r * 32 + lane];
    int half = lane & 1, mm = lane >> 1;
    int qb = r * 8 + half * 4;
    int xbase = (qb / 360) * 36 + (qb % 36);       // consecutive, 16B-aligned
    float* up = g_u + (size_t)r * 16 + mm;

    #pragma unroll 4
    for (int b = 0; b < 256; b++) {
        float4 x4 = *reinterpret_cast<const float4*>(&g_h2[(size_t)b * 9216 + xbase]);
        float p = w4.x * x4.x + w4.y * x4.y + w4.z * x4.z + w4.w * x4.w;
        float s = p + __shfl_xor_sync(0xFFFFFFFFu, p, 1);
        if (half == 0) up[(size_t)b * 184320] = s;
    }
}

// ---------------- dynamic routing (3 iters), one block per batch ----------------
__global__ __launch_bounds__(288)
void routing_kernel(const float* __restrict__ y, const float* __restrict__ bias_r,
                    float* __restrict__ out) {
    __shared__ float spart[18 * 160];
    __shared__ float sfull[160];
    __shared__ __align__(16) float sv[160];
    __shared__ float sscale[16];
    int b = blockIdx.x, t = threadIdx.x;
    const float* ub = g_u + (size_t)b * 184320;
    float* sb = g_blog + (size_t)b * 11520;
    int g = t >> 4, m = t & 15;

    for (int iter = 0; iter < 3; ++iter) {
        float acc[10];
        #pragma unroll
        for (int j = 0; j < 10; j++) acc[j] = 0.f;
        int i0 = g * 64;
        for (int i = i0; i < i0 + 64; i++) {
            float c[10];
            if (iter == 0) {
                #pragma unroll
                for (int j = 0; j < 10; j++) c[j] = 0.1f;
            } else {
                float mx = -1e30f;
                #pragma unroll
                for (int j = 0; j < 10; j++) { c[j] = sb[i * 10 + j]; mx = fmaxf(mx, c[j]); }
                float s = 0.f;
                #pragma unroll
                for (int j = 0; j < 10; j++) { c[j] = __expf(c[j] - mx); s += c[j]; }
                float inv = 1.f / s;
                #pragma unroll
                for (int j = 0; j < 10; j++) c[j] *= inv;
            }
            const float* up = ub + (size_t)i * 160 + m;
            #pragma unroll
            for (int j = 0; j < 10; j++) acc[j] += c[j] * up[j * 16];
        }
        #pragma unroll
        for (int j = 0; j < 10; j++) spart[g * 160 + j * 16 + m] = acc[j];
        __syncthreads();

        if (t < 160) {
            float s = bias_r[t];
            #pragma unroll
            for (int g2 = 0; g2 < 18; g2++) s += spart[g2 * 160 + t];
            sfull[t] = s;
        }
        __syncthreads();
        if (t < 10) {
            float n2 = 0.f;
            #pragma unroll
            for (int mm = 0; mm < 16; mm++) { float v = sfull[t * 16 + mm]; n2 += v * v; }
            sscale[t] = (n2 / (1.f + n2)) / sqrtf(n2 + EPSF);
        }
        __syncthreads();
        if (t < 160) sv[t] = sfull[t] * sscale[t >> 4];
        __syncthreads();

        if (iter < 2) {
            for (int idx = t; idx < 11520; idx += 288) {
                int j = idx % 10;
                const float4* up4 = (const float4*)(ub + (size_t)idx * 16);
                const float4* vv4 = (const float4*)(sv + j * 16);
                float d = 0.f;
                #pragma unroll
                for (int q = 0; q < 4; q++) {
                    float4 a = up4[q], v4 = vv4[q];
                    d += a.x * v4.x + a.y * v4.y + a.z * v4.z + a.w * v4.w;
                }
                if (iter == 0) sb[idx] = d; else sb[idx] += d;
            }
        }
        __syncthreads();
    }
    if (t < 10) {
        float n2 = 0.f;
        #pragma unroll
        for (int mm = 0; mm < 16; mm++) { float v = sv[t * 16 + mm]; n2 += v * v; }
        out[b * 10 + t] = sqrtf(n2 + EPSF);
    }
    if (t < 16) {
        float s = 0.f;
        const float* yb = y + b * 10;
        #pragma unroll
        for (int tt = 0; tt < 10; tt++) s += sv[t * 10 + tt] * yb[tt];
        g_masked[b * 16 + t] = s;
    }
}

// ---------------- FC GEMM ----------------
__global__ void gemm_kernel(const float* __restrict__ Wt, const float* __restrict__ bias,
                            float* __restrict__ out, int N, int K, int which) {
    __shared__ float As[16][16];
    __shared__ float Bs[16][17];
    const float* A; float* C;
    if (which == 0)      { A = g_masked; C = g_fc1; }
    else if (which == 1) { A = g_fc1;    C = g_fc2; }
    else                 { A = g_fc2;    C = out + 2560; }
    int tx = threadIdx.x, ty = threadIdx.y;
    int n0 = blockIdx.x * 16, m0 = blockIdx.y * 16;
    float acc = 0.f;
    for (int k0 = 0; k0 < K; k0 += 16) {
        As[ty][tx] = A[(size_t)(m0 + ty) * K + k0 + tx];
        Bs[ty][tx] = Wt[(size_t)(n0 + ty) * K + k0 + tx];
        __syncthreads();
        #pragma unroll
        for (int kk = 0; kk < 16; kk++) acc += As[ty][kk] * Bs[tx][kk];
        __syncthreads();
    }
    acc += bias[n0 + tx];
    if (which == 2) acc = 1.f / (1.f + expf(-acc));
    C[(size_t)(m0 + ty) * N + n0 + tx] = acc;
}

// ---------------- launch ----------------
extern "C" void kernel_launch(void* const* d_in, const int* in_sizes, int n_in,
                              void* d_out, int out_size) {
    (void)in_sizes; (void)n_in; (void)out_size;
    const float* x   = (const float*)d_in[0];
    const float* y   = (const float*)d_in[1];
    const float* c1w = (const float*)d_in[2];
    const float* c1b = (const float*)d_in[3];
    const float* c2w = (const float*)d_in[4];
    const float* c2b = (const float*)d_in[5];
    const float* W   = (const float*)d_in[6];
    const float* br  = (const float*)d_in[7];
    const float* f1w = (const float*)d_in[8];
    const float* f1b = (const float*)d_in[9];
    const float* f2w = (const float*)d_in[10];
    const float* f2b = (const float*)d_in[11];
    const float* f3w = (const float*)d_in[12];
    const float* f3b = (const float*)d_in[13];
    float* out = (float*)d_out;

    prep_w_kernel<<<dim3(81, 256), 256>>>(c2w);
    conv1_kernel<<<dim3(8, 256), 256>>>(x, c1w, c1b);
    caps1_mma_kernel<<<dim3(2, 72), 256, SMEM_C1>>>(c2b);
    u_kernel<<<1440, 256>>>(W);
    routing_kernel<<<256, 288>>>(y, br, out);
    gemm_kernel<<<dim3(32, 16), dim3(16, 16)>>>(f1w, f1b, out, 512, 16, 0);
    gemm_kernel<<<dim3(64, 16), dim3(16, 16)>>>(f2w, f2b, out, 1024, 512, 1);
    gemm_kernel<<<dim3(49, 16), dim3(16, 16)>>>(f3w, f3b, out, 784, 1024, 2);
}

// round 12
// speedup vs baseline: 1.1235x; 1.1235x over previous
#include <cuda_runtime.h>
#include <cuda_fp16.h>
#include <cstdint>

#define EPSF 1e-9f
typedef unsigned long long u64;
typedef unsigned int u32;

// ---------------- persistent device scratch ----------------
__device__ __half g_h1h[256*400*256];          // conv1 out NHWC fp16  52MB
__device__ __half g_wh[256*20736];             // caps1 W [co][tap*256+ci] fp16
__device__ float g_h2[256*256*36];             // caps1 out (relu'd)  [b][co][36]
__device__ __half g_u[256u*1152*10*16];        // prediction vectors fp16  94MB
__device__ float g_blog[256*11520];            // routing logits
__device__ float g_masked[256*16];
__device__ float g_fc1[256*512];
__device__ float g_fc2[256*1024];

// ---------------- helpers ----------------
__device__ __forceinline__ void fma2(u64& acc, u64 a, u64 b) {
    asm("fma.rn.f32x2 %0, %1, %2, %0;" : "+l"(acc) : "l"(a), "l"(b));
}
__device__ __forceinline__ u64 pack2(float lo, float hi) {
    u64 r; unsigned il = __float_as_uint(lo), ih = __float_as_uint(hi);
    asm("mov.b64 %0, {%1, %2};" : "=l"(r) : "r"(il), "r"(ih));
    return r;
}
__device__ __forceinline__ u64 pack_dup(float v) {
    u64 r; unsigned iv = __float_as_uint(v);
    asm("mov.b64 %0, {%1, %1};" : "=l"(r) : "r"(iv));
    return r;
}
__device__ __forceinline__ void unpack2(u64 v, float& lo, float& hi) {
    asm("mov.b64 {%0, %1}, %2;" : "=f"(lo), "=f"(hi) : "l"(v));
}
__device__ __forceinline__ u32 smem_u32(const void* p) {
    u32 a;
    asm("{ .reg .u64 t; cvta.to.shared.u64 t, %1; cvt.u32.u64 %0, t; }" : "=r"(a) : "l"(p));
    return a;
}
__device__ __forceinline__ void cp16(u32 dst, const void* src) {
    asm volatile("cp.async.cg.shared.global [%0], [%1], 16;" :: "r"(dst), "l"(src) : "memory");
}
__device__ __forceinline__ void cp_commit() { asm volatile("cp.async.commit_group;" ::: "memory"); }
#define CP_WAIT(n) asm volatile("cp.async.wait_group %0;" :: "n"(n) : "memory")

// fp16 warp MMA m16n8k16, fp32 accum
#define MMAF16(c, a, b0, b1) \
    asm volatile("mma.sync.aligned.m16n8k16.row.col.f32.f16.f16.f32 " \
        "{%0,%1,%2,%3}, {%4,%5,%6,%7}, {%8,%9}, {%0,%1,%2,%3};" \
        : "+f"((c)[0]), "+f"((c)[1]), "+f"((c)[2]), "+f"((c)[3]) \
        : "r"((a)[0]), "r"((a)[1]), "r"((a)[2]), "r"((a)[3]), "r"(b0), "r"(b1))

// ---------------- weight prep: w[co][ci][9][9] fp32 -> g_wh[co][tap*256+ci] fp16 ----------------
__global__ void prep_w_kernel(const float* __restrict__ w) {
    int k  = blockIdx.x * 256 + threadIdx.x;   // 0..20735 (grid.x = 81)
    int co = blockIdx.y;
    int tap = k >> 8, ci = k & 255;
    g_wh[(size_t)co * 20736 + k] = __float2half(w[(size_t)co * 20736 + ci * 81 + tap]);
}

// ---------------- conv1: (B,1,28,28) -> relu -> NHWC fp16 (B,20,20,256) ----------------
__global__ __launch_bounds__(256)
void conv1_kernel(const float* __restrict__ x, const float* __restrict__ w,
                  const float* __restrict__ bias) {
    __shared__ float img[784];
    __shared__ float ws[2592];                 // layout [tap][32 co]
    int b = blockIdx.y, co0 = blockIdx.x * 32;
    int tid = threadIdx.x;
    for (int i = tid; i < 784; i += 256) img[i] = x[b * 784 + i];
    for (int i = tid; i < 2592; i += 256) {
        int t = i >> 5, c = i & 31;
        ws[i] = w[(co0 + c) * 81 + t];
    }
    u64 b2[16];
    #pragma unroll
    for (int c = 0; c < 16; c++) b2[c] = pack2(bias[co0 + 2*c], bias[co0 + 2*c + 1]);
    __syncthreads();

    for (int p = tid; p < 400; p += 256) {
        int oy = p / 20, ox = p % 20;
        u64 acc[16];
        #pragma unroll
        for (int c = 0; c < 16; c++) acc[c] = b2[c];
        #pragma unroll 1
        for (int dy = 0; dy < 9; dy++) {
            const float* row = img + (oy + dy) * 28 + ox;
            u64 rr[9];
            #pragma unroll
            for (int dx = 0; dx < 9; dx++) rr[dx] = pack_dup(row[dx]);
            #pragma unroll
            for (int dx = 0; dx < 9; dx++) {
                const u64* wp = (const u64*)(ws + (dy * 9 + dx) * 32);
                #pragma unroll
                for (int c = 0; c < 16; c++) fma2(acc[c], wp[c], rr[dx]);
            }
        }
        size_t base = ((size_t)b * 400 + p) * 256 + co0;
        #pragma unroll
        for (int c = 0; c < 16; c++) {
            float lo, hi; unpack2(acc[c], lo, hi);
            *reinterpret_cast<__half2*>(&g_h1h[base + 2*c]) =
                __halves2half2(__float2half(fmaxf(lo, 0.f)), __float2half(fmaxf(hi, 0.f)));
        }
    }
}

// ---------------- caps1 via mma.sync fp16: C[9216,256] = A[9216,20736] @ W^T ----------------
// 256 threads (8 warps 4x2), CTA tile M=128 x N=128, grid 144 (~1 CTA/SM).
// K-step 16, 1296 steps, 3-stage cp.async pipeline.
// stage: A 128x48B = 6K | B 128x48B = 6K -> 12KB; 3 stages = 36KB.
static constexpr int CSTG = 12288;
static constexpr u32 SMEM_C1 = 3 * CSTG;   // 36864 < 48KB default

__global__ __launch_bounds__(256, 1)
void caps1_mma_kernel(const float* __restrict__ bias) {
    extern __shared__ char smem[];
    u32 sm = smem_u32(smem);
    int tid = threadIdx.x;
    int n0 = blockIdx.x * 128, m0 = blockIdx.y * 128;

    // loader: rw = tid>>1 (0..127), ch = tid&1 (16B chunk = 8 fp16); 2 cp16/thread/step
    int rw = tid >> 1, ch = tid & 1;
    int pl = m0 + rw;
    int pb = pl / 36, prr = pl % 36, loy = prr / 6, lox = prr % 6;
    u32 aPix = (u32)((pb * 20 + 2 * loy) * 20 + 2 * lox) * 256 + ch * 8;
    u32 bRow = (u32)(n0 + rw) * 20736 + ch * 8;
    u32 rowOff = (u32)(rw * 48 + ch * 16);

    auto load_stage = [&](int s, int step) {
        u32 base = sm + s * CSTG;
        int tap = step >> 4, ci0 = (step & 15) * 16;
        int dy = tap / 9, dx = tap - dy * 9;
        u32 asrc = aPix + (u32)(dy * 20 + dx) * 256 + ci0;
        u32 bs = (u32)tap * 256 + ci0;
        cp16(base + rowOff,        g_h1h + asrc);
        cp16(base + 6144 + rowOff, g_wh + bRow + bs);
        cp_commit();
    };

    int wid = tid >> 5, lane = tid & 31;
    int wm = wid & 3, wn = wid >> 2;               // warp tile: M 32, N 64
    int g = lane >> 2, tc = lane & 3;

    float c[2][8][4];
    #pragma unroll
    for (int i = 0; i < 2; i++)
        #pragma unroll
        for (int j = 0; j < 8; j++)
            #pragma unroll
            for (int q = 0; q < 4; q++) c[i][j][q] = 0.f;

    load_stage(0, 0);
    load_stage(1, 1);

    #pragma unroll 1
    for (int step = 0; step < 1296; step++) {
        int cur = step % 3;
        if (step + 1 < 1296) { CP_WAIT(1); } else { CP_WAIT(0); }
        __syncthreads();                       // stage cur ready; stage (cur+2)%3 free
        if (step + 2 < 1296) load_stage((step + 2) % 3, step + 2);

        const u32* Ah = (const u32*)(smem + cur * CSTG);
        const u32* Bh = Ah + 1536;     // +6144B
        u32 ah[2][4];
        #pragma unroll
        for (int tm = 0; tm < 2; tm++) {
            int r = wm * 32 + tm * 16 + g;
            ah[tm][0] = Ah[r * 12 + tc];       ah[tm][1] = Ah[(r + 8) * 12 + tc];
            ah[tm][2] = Ah[r * 12 + tc + 4];   ah[tm][3] = Ah[(r + 8) * 12 + tc + 4];
        }
        #pragma unroll
        for (int tn = 0; tn < 8; tn++) {
            int n = wn * 64 + tn * 8 + g;
            u32 bh0 = Bh[n * 12 + tc], bh1 = Bh[n * 12 + tc + 4];
            #pragma unroll
            for (int tm = 0; tm < 2; tm++)
                MMAF16(c[tm][tn], ah[tm], bh0, bh1);
        }
    }
    __syncthreads();

    // epilogue: bias + relu -> g_h2[b][co][36]
    #pragma unroll
    for (int tm = 0; tm < 2; tm++) {
        int r0 = m0 + wm * 32 + tm * 16 + g;
        int b0i = r0 / 36, rr0 = r0 % 36;
        int r1 = r0 + 8;
        int b1i = r1 / 36, rr1 = r1 % 36;
        float* d0 = g_h2 + (size_t)b0i * 9216 + rr0;
        float* d1 = g_h2 + (size_t)b1i * 9216 + rr1;
        #pragma unroll
        for (int tn = 0; tn < 8; tn++) {
            int cc = n0 + wn * 64 + tn * 8 + tc * 2;
            float bv0 = bias[cc], bv1 = bias[cc + 1];
            d0[(size_t)cc * 36]       = fmaxf(c[tm][tn][0] + bv0, 0.f);
            d0[(size_t)(cc + 1) * 36] = fmaxf(c[tm][tn][1] + bv1, 0.f);
            d1[(size_t)cc * 36]       = fmaxf(c[tm][tn][2] + bv0, 0.f);
            d1[(size_t)(cc + 1) * 36] = fmaxf(c[tm][tn][3] + bv1, 0.f);
        }
    }
}

// ---------------- u = Wj @ x_tile, warp-per-row (batch-major, R10 shape) ----------------
__global__ __launch_bounds__(256)
void u_kernel(const float* __restrict__ W) {
    __shared__ __align__(16) float sx[9216];
    int b = blockIdx.x, chunk = blockIdx.y;
    int tid = threadIdx.x, wid = tid >> 5, lane = tid & 31;
    const float* h2b = g_h2 + (size_t)b * 9216;
    for (int i = tid; i < 9216; i += 256) sx[i] = h2b[i];
    __syncthreads();

    int half = lane & 1, mm = lane >> 1;
    __half* ub = g_u + (size_t)b * 184320;

    #pragma unroll 4
    for (int k = 0; k < 180; k++) {
        int r = chunk * 1440 + wid + 8 * k;
        float4 w4 = reinterpret_cast<const float4*>(W)[(size_t)r * 32 + lane];
        int qb = r * 8 + half * 4;
        int base = (qb / 360) * 36 + (qb % 36);
        float4 x4 = *reinterpret_cast<const float4*>(&sx[base]);
        float p = w4.x * x4.x + w4.y * x4.y + w4.z * x4.z + w4.w * x4.w;
        float s = p + __shfl_xor_sync(0xFFFFFFFFu, p, 1);
        if (half == 0) ub[(size_t)r * 16 + mm] = __float2half(s);
    }
}

// ---------------- dynamic routing (3 iters), one block per batch ----------------
__global__ __launch_bounds__(288)
void routing_kernel(const float* __restrict__ y, const float* __restrict__ bias_r,
                    float* __restrict__ out) {
    __shared__ float spart[18 * 160];
    __shared__ float sfull[160];
    __shared__ __align__(16) float sv[160];
    __shared__ float sscale[16];
    int b = blockIdx.x, t = threadIdx.x;
    const __half* ub = g_u + (size_t)b * 184320;
    float* sb = g_blog + (size_t)b * 11520;
    int g = t >> 4, m = t & 15;

    for (int iter = 0; iter < 3; ++iter) {
        float acc[10];
        #pragma unroll
        for (int j = 0; j < 10; j++) acc[j] = 0.f;
        int i0 = g * 64;
        for (int i = i0; i < i0 + 64; i++) {
            float c[10];
            if (iter == 0) {
                #pragma unroll
                for (int j = 0; j < 10; j++) c[j] = 0.1f;
            } else {
                float mx = -1e30f;
                #pragma unroll
                for (int j = 0; j < 10; j++) { c[j] = sb[i * 10 + j]; mx = fmaxf(mx, c[j]); }
                float s = 0.f;
                #pragma unroll
                for (int j = 0; j < 10; j++) { c[j] = __expf(c[j] - mx); s += c[j]; }
                float inv = 1.f / s;
                #pragma unroll
                for (int j = 0; j < 10; j++) c[j] *= inv;
            }
            const __half* up = ub + (size_t)i * 160 + m;
            #pragma unroll
            for (int j = 0; j < 10; j++) acc[j] += c[j] * __half2float(up[j * 16]);
        }
        #pragma unroll
        for (int j = 0; j < 10; j++) spart[g * 160 + j * 16 + m] = acc[j];
        __syncthreads();

        if (t < 160) {
            float s = bias_r[t];
            #pragma unroll
            for (int g2 = 0; g2 < 18; g2++) s += spart[g2 * 160 + t];
            sfull[t] = s;
        }
        __syncthreads();
        if (t < 10) {
            float n2 = 0.f;
            #pragma unroll
            for (int mm = 0; mm < 16; mm++) { float v = sfull[t * 16 + mm]; n2 += v * v; }
            sscale[t] = (n2 / (1.f + n2)) / sqrtf(n2 + EPSF);
        }
        __syncthreads();
        if (t < 160) sv[t] = sfull[t] * sscale[t >> 4];
        __syncthreads();

        if (iter < 2) {                                   // agreement update
            for (int idx = t; idx < 11520; idx += 288) {
                int j = idx % 10;
                const __half2* up2 = (const __half2*)(ub + (size_t)idx * 16);
                const float* vj = sv + j * 16;
                float d = 0.f;
                #pragma unroll
                for (int q = 0; q < 8; q++) {
                    float2 a = __half22float2(up2[q]);
                    d += a.x * vj[2 * q] + a.y * vj[2 * q + 1];
                }
                if (iter == 0) sb[idx] = d; else sb[idx] += d;
            }
        }
        __syncthreads();
    }
    if (t < 10) {
        float n2 = 0.f;
        #pragma unroll
        for (int mm = 0; mm < 16; mm++) { float v = sv[t * 16 + mm]; n2 += v * v; }
        out[b * 10 + t] = sqrtf(n2 + EPSF);
    }
    if (t < 16) {
        float s = 0.f;
        const float* yb = y + b * 10;
        #pragma unroll
        for (int tt = 0; tt < 10; tt++) s += sv[t * 10 + tt] * yb[tt];
        g_masked[b * 16 + t] = s;
    }
}

// ---------------- FC GEMM ----------------
__global__ void gemm_kernel(const float* __restrict__ Wt, const float* __restrict__ bias,
                            float* __restrict__ out, int N, int K, int which) {
    __shared__ float As[16][16];
    __shared__ float Bs[16][17];
    const float* A; float* C;
    if (which == 0)      { A = g_masked; C = g_fc1; }
    else if (which == 1) { A = g_fc1;    C = g_fc2; }
    else                 { A = g_fc2;    C = out + 2560; }
    int tx = threadIdx.x, ty = threadIdx.y;
    int n0 = blockIdx.x * 16, m0 = blockIdx.y * 16;
    float acc = 0.f;
    for (int k0 = 0; k0 < K; k0 += 16) {
        As[ty][tx] = A[(size_t)(m0 + ty) * K + k0 + tx];
        Bs[ty][tx] = Wt[(size_t)(n0 + ty) * K + k0 + tx];
        __syncthreads();
        #pragma unroll
        for (int kk = 0; kk < 16; kk++) acc += As[ty][kk] * Bs[tx][kk];
        __syncthreads();
    }
    acc += bias[n0 + tx];
    if (which == 2) acc = 1.f / (1.f + expf(-acc));
    C[(size_t)(m0 + ty) * N + n0 + tx] = acc;
}

// ---------------- launch ----------------
extern "C" void kernel_launch(void* const* d_in, const int* in_sizes, int n_in,
                              void* d_out, int out_size) {
    (void)in_sizes; (void)n_in; (void)out_size;
    const float* x   = (const float*)d_in[0];
    const float* y   = (const float*)d_in[1];
    const float* c1w = (const float*)d_in[2];
    const float* c1b = (const float*)d_in[3];
    const float* c2w = (const float*)d_in[4];
    const float* c2b = (const float*)d_in[5];
    const float* W   = (const float*)d_in[6];
    const float* br  = (const float*)d_in[7];
    const float* f1w = (const float*)d_in[8];
    const float* f1b = (const float*)d_in[9];
    const float* f2w = (const float*)d_in[10];
    const float* f2b = (const float*)d_in[11];
    const float* f3w = (const float*)d_in[12];
    const float* f3b = (const float*)d_in[13];
    float* out = (float*)d_out;

    prep_w_kernel<<<dim3(81, 256), 256>>>(c2w);
    conv1_kernel<<<dim3(8, 256), 256>>>(x, c1w, c1b);
    caps1_mma_kernel<<<dim3(2, 72), 256, SMEM_C1>>>(c2b);
    u_kernel<<<dim3(256, 8), 256>>>(W);
    routing_kernel<<<256, 288>>>(y, br, out);
    gemm_kernel<<<dim3(32, 16), dim3(16, 16)>>>(f1w, f1b, out, 512, 16, 0);
    gemm_kernel<<<dim3(64, 16), dim3(16, 16)>>>(f2w, f2b, out, 1024, 512, 1);
    gemm_kernel<<<dim3(49, 16), dim3(16, 16)>>>(f3w, f3b, out, 784, 1024, 2);
}

// round 13
// speedup vs baseline: 1.2100x; 1.0771x over previous
#include <cuda_runtime.h>
#include <cuda_fp16.h>
#include <cstdint>

#define EPSF 1e-9f
typedef unsigned long long u64;
typedef unsigned int u32;

// ---------------- persistent device scratch ----------------
__device__ __half g_h1h[256*400*256];          // conv1 out NHWC fp16  52MB
__device__ __half g_wh[256*20736];             // caps1 W [co][tap*256+ci] fp16
__device__ float g_h2[256*256*36];             // caps1 out (relu'd)  [b][co][36]
__device__ __half g_u[256u*1152*10*16];        // prediction vectors fp16  94MB
__device__ float g_blog[256*11520];            // routing logits
__device__ float g_masked[256*16];
__device__ float g_fc1[256*512];
__device__ float g_fc2[256*1024];

// ---------------- helpers ----------------
__device__ __forceinline__ void fma2(u64& acc, u64 a, u64 b) {
    asm("fma.rn.f32x2 %0, %1, %2, %0;" : "+l"(acc) : "l"(a), "l"(b));
}
__device__ __forceinline__ u64 pack2(float lo, float hi) {
    u64 r; unsigned il = __float_as_uint(lo), ih = __float_as_uint(hi);
    asm("mov.b64 %0, {%1, %2};" : "=l"(r) : "r"(il), "r"(ih));
    return r;
}
__device__ __forceinline__ u64 pack_dup(float v) {
    u64 r; unsigned iv = __float_as_uint(v);
    asm("mov.b64 %0, {%1, %1};" : "=l"(r) : "r"(iv));
    return r;
}
__device__ __forceinline__ void unpack2(u64 v, float& lo, float& hi) {
    asm("mov.b64 {%0, %1}, %2;" : "=f"(lo), "=f"(hi) : "l"(v));
}
__device__ __forceinline__ u32 smem_u32(const void* p) {
    u32 a;
    asm("{ .reg .u64 t; cvta.to.shared.u64 t, %1; cvt.u32.u64 %0, t; }" : "=r"(a) : "l"(p));
    return a;
}
__device__ __forceinline__ void cp16(u32 dst, const void* src) {
    asm volatile("cp.async.cg.shared.global [%0], [%1], 16;" :: "r"(dst), "l"(src) : "memory");
}
__device__ __forceinline__ void cp_commit() { asm volatile("cp.async.commit_group;" ::: "memory"); }
#define CP_WAIT(n) asm volatile("cp.async.wait_group %0;" :: "n"(n) : "memory")

// fp16 warp MMA m16n8k16, fp32 accum
#define MMAF16(c, a, b0, b1) \
    asm volatile("mma.sync.aligned.m16n8k16.row.col.f32.f16.f16.f32 " \
        "{%0,%1,%2,%3}, {%4,%5,%6,%7}, {%8,%9}, {%0,%1,%2,%3};" \
        : "+f"((c)[0]), "+f"((c)[1]), "+f"((c)[2]), "+f"((c)[3]) \
        : "r"((a)[0]), "r"((a)[1]), "r"((a)[2]), "r"((a)[3]), "r"(b0), "r"(b1))

// ---------------- weight prep: w[co][ci][9][9] fp32 -> g_wh[co][tap*256+ci] fp16 ----------------
__global__ void prep_w_kernel(const float* __restrict__ w) {
    int k  = blockIdx.x * 256 + threadIdx.x;   // 0..20735 (grid.x = 81)
    int co = blockIdx.y;
    int tap = k >> 8, ci = k & 255;
    g_wh[(size_t)co * 20736 + k] = __float2half(w[(size_t)co * 20736 + ci * 81 + tap]);
}

// ---------------- conv1: (B,1,28,28) -> relu -> NHWC fp16 (B,20,20,256) ----------------
// Stores staged through smem so global writes are coalesced runs.
__global__ __launch_bounds__(256)
void conv1_kernel(const float* __restrict__ x, const float* __restrict__ w,
                  const float* __restrict__ bias) {
    __shared__ float img[784];
    __shared__ float ws[2592];                 // layout [tap][32 co]
    __shared__ __half2 sh[400 * 16];           // [pixel][co-pair], 25.6KB
    int b = blockIdx.y, co0 = blockIdx.x * 32;
    int tid = threadIdx.x;
    for (int i = tid; i < 784; i += 256) img[i] = x[b * 784 + i];
    for (int i = tid; i < 2592; i += 256) {
        int t = i >> 5, c = i & 31;
        ws[i] = w[(co0 + c) * 81 + t];
    }
    u64 b2[16];
    #pragma unroll
    for (int c = 0; c < 16; c++) b2[c] = pack2(bias[co0 + 2*c], bias[co0 + 2*c + 1]);
    __syncthreads();

    for (int p = tid; p < 400; p += 256) {
        int oy = p / 20, ox = p % 20;
        u64 acc[16];
        #pragma unroll
        for (int c = 0; c < 16; c++) acc[c] = b2[c];
        #pragma unroll 1
        for (int dy = 0; dy < 9; dy++) {
            const float* row = img + (oy + dy) * 28 + ox;
            u64 rr[9];
            #pragma unroll
            for (int dx = 0; dx < 9; dx++) rr[dx] = pack_dup(row[dx]);
            #pragma unroll
            for (int dx = 0; dx < 9; dx++) {
                const u64* wp = (const u64*)(ws + (dy * 9 + dx) * 32);
                #pragma unroll
                for (int c = 0; c < 16; c++) fma2(acc[c], wp[c], rr[dx]);
            }
        }
        #pragma unroll
        for (int c = 0; c < 16; c++) {
            float lo, hi; unpack2(acc[c], lo, hi);
            sh[p * 16 + c] =
                __halves2half2(__float2half(fmaxf(lo, 0.f)), __float2half(fmaxf(hi, 0.f)));
        }
    }
    __syncthreads();
    // coalesced copy out: half2 idx i -> pixel i>>4, co-pair i&15
    __half2* dst = reinterpret_cast<__half2*>(g_h1h) + ((size_t)b * 400) * 128 + (co0 >> 1);
    for (int i = tid; i < 6400; i += 256) {
        int p = i >> 4, c = i & 15;
        dst[(size_t)p * 128 + c] = sh[i];
    }
}

// ---------------- caps1 via mma.sync fp16: C[9216,256] = A[9216,20736] @ W^T ----------------
// 256 threads (8 warps 4x2), CTA tile M=128 x N=128, grid 144 (~1 CTA/SM).
// K-step 16, 1296 steps, 4-stage cp.async pipeline (48KB exactly).
static constexpr int CSTG = 12288;
static constexpr u32 SMEM_C1 = 4 * CSTG;   // 49152 = default limit

__global__ __launch_bounds__(256, 1)
void caps1_mma_kernel(const float* __restrict__ bias) {
    extern __shared__ char smem[];
    u32 sm = smem_u32(smem);
    int tid = threadIdx.x;
    int n0 = blockIdx.x * 128, m0 = blockIdx.y * 128;

    // loader: rw = tid>>1 (0..127), ch = tid&1 (16B chunk = 8 fp16); 2 cp16/thread/step
    int rw = tid >> 1, ch = tid & 1;
    int pl = m0 + rw;
    int pb = pl / 36, prr = pl % 36, loy = prr / 6, lox = prr % 6;
    u32 aPix = (u32)((pb * 20 + 2 * loy) * 20 + 2 * lox) * 256 + ch * 8;
    u32 bRow = (u32)(n0 + rw) * 20736 + ch * 8;
    u32 rowOff = (u32)(rw * 48 + ch * 16);

    auto load_stage = [&](int s, int step) {
        u32 base = sm + s * CSTG;
        int tap = step >> 4, ci0 = (step & 15) * 16;
        int dy = tap / 9, dx = tap - dy * 9;
        u32 asrc = aPix + (u32)(dy * 20 + dx) * 256 + ci0;
        u32 bs = (u32)tap * 256 + ci0;
        cp16(base + rowOff,        g_h1h + asrc);
        cp16(base + 6144 + rowOff, g_wh + bRow + bs);
        cp_commit();
    };

    int wid = tid >> 5, lane = tid & 31;
    int wm = wid & 3, wn = wid >> 2;               // warp tile: M 32, N 64
    int g = lane >> 2, tc = lane & 3;

    float c[2][8][4];
    #pragma unroll
    for (int i = 0; i < 2; i++)
        #pragma unroll
        for (int j = 0; j < 8; j++)
            #pragma unroll
            for (int q = 0; q < 4; q++) c[i][j][q] = 0.f;

    load_stage(0, 0);
    load_stage(1, 1);
    load_stage(2, 2);

    #pragma unroll 1
    for (int step = 0; step < 1296; step++) {
        int cur = step & 3;
        if (step < 1293) { CP_WAIT(2); } else { CP_WAIT(0); }   // stage cur complete (race-free tail)
        __syncthreads();                       // all warps done with stage being overwritten
        if (step + 3 < 1296) load_stage((step + 3) & 3, step + 3);

        const u32* Ah = (const u32*)(smem + cur * CSTG);
        const u32* Bh = Ah + 1536;     // +6144B
        u32 ah[2][4];
        #pragma unroll
        for (int tm = 0; tm < 2; tm++) {
            int r = wm * 32 + tm * 16 + g;
            ah[tm][0] = Ah[r * 12 + tc];       ah[tm][1] = Ah[(r + 8) * 12 + tc];
            ah[tm][2] = Ah[r * 12 + tc + 4];   ah[tm][3] = Ah[(r + 8) * 12 + tc + 4];
        }
        #pragma unroll
        for (int tn = 0; tn < 8; tn++) {
            int n = wn * 64 + tn * 8 + g;
            u32 bh0 = Bh[n * 12 + tc], bh1 = Bh[n * 12 + tc + 4];
            #pragma unroll
            for (int tm = 0; tm < 2; tm++)
                MMAF16(c[tm][tn], ah[tm], bh0, bh1);
        }
    }
    __syncthreads();

    // epilogue: bias + relu -> g_h2[b][co][36]
    #pragma unroll
    for (int tm = 0; tm < 2; tm++) {
        int r0 = m0 + wm * 32 + tm * 16 + g;
        int b0i = r0 / 36, rr0 = r0 % 36;
        int r1 = r0 + 8;
        int b1i = r1 / 36, rr1 = r1 % 36;
        float* d0 = g_h2 + (size_t)b0i * 9216 + rr0;
        float* d1 = g_h2 + (size_t)b1i * 9216 + rr1;
        #pragma unroll
        for (int tn = 0; tn < 8; tn++) {
            int cc = n0 + wn * 64 + tn * 8 + tc * 2;
            float bv0 = bias[cc], bv1 = bias[cc + 1];
            d0[(size_t)cc * 36]       = fmaxf(c[tm][tn][0] + bv0, 0.f);
            d0[(size_t)(cc + 1) * 36] = fmaxf(c[tm][tn][1] + bv1, 0.f);
            d1[(size_t)cc * 36]       = fmaxf(c[tm][tn][2] + bv0, 0.f);
            d1[(size_t)(cc + 1) * 36] = fmaxf(c[tm][tn][3] + bv1, 0.f);
        }
    }
}

// ---------------- u = Wj @ x_tile, warp-per-row (batch-major) ----------------
__global__ __launch_bounds__(256)
void u_kernel(const float* __restrict__ W) {
    __shared__ __align__(16) float sx[9216];
    int b = blockIdx.x, chunk = blockIdx.y;
    int tid = threadIdx.x, wid = tid >> 5, lane = tid & 31;
    const float* h2b = g_h2 + (size_t)b * 9216;
    for (int i = tid; i < 9216; i += 256) sx[i] = h2b[i];
    __syncthreads();

    int half = lane & 1, mm = lane >> 1;
    __half* ub = g_u + (size_t)b * 184320;

    #pragma unroll 4
    for (int k = 0; k < 180; k++) {
        int r = chunk * 1440 + wid + 8 * k;
        float4 w4 = reinterpret_cast<const float4*>(W)[(size_t)r * 32 + lane];
        int qb = r * 8 + half * 4;
        int base = (qb / 360) * 36 + (qb % 36);
        float4 x4 = *reinterpret_cast<const float4*>(&sx[base]);
        float p = w4.x * x4.x + w4.y * x4.y + w4.z * x4.z + w4.w * x4.w;
        float s = p + __shfl_xor_sync(0xFFFFFFFFu, p, 1);
        if (half == 0) ub[(size_t)r * 16 + mm] = __float2half(s);
    }
}

// ---------------- dynamic routing (3 iters), one block per batch, 576 threads ----------------
// g = t/16 in [0,36) handles 32 i's; m = t%16.
__global__ __launch_bounds__(576)
void routing_kernel(const float* __restrict__ y, const float* __restrict__ bias_r,
                    float* __restrict__ out) {
    __shared__ float spart[36 * 160];
    __shared__ float sfull[160];
    __shared__ __align__(16) float sv[160];
    __shared__ float sscale[16];
    int b = blockIdx.x, t = threadIdx.x;
    const __half* ub = g_u + (size_t)b * 184320;
    float* sb = g_blog + (size_t)b * 11520;
    int g = t >> 4, m = t & 15;

    for (int iter = 0; iter < 3; ++iter) {
        float acc[10];
        #pragma unroll
        for (int j = 0; j < 10; j++) acc[j] = 0.f;
        int i0 = g * 32;
        for (int i = i0; i < i0 + 32; i++) {
            float c[10];
            if (iter == 0) {
                #pragma unroll
                for (int j = 0; j < 10; j++) c[j] = 0.1f;
            } else {
                float mx = -1e30f;
                #pragma unroll
                for (int j = 0; j < 10; j++) { c[j] = sb[i * 10 + j]; mx = fmaxf(mx, c[j]); }
                float s = 0.f;
                #pragma unroll
                for (int j = 0; j < 10; j++) { c[j] = __expf(c[j] - mx); s += c[j]; }
                float inv = 1.f / s;
                #pragma unroll
                for (int j = 0; j < 10; j++) c[j] *= inv;
            }
            const __half* up = ub + (size_t)i * 160 + m;
            #pragma unroll
            for (int j = 0; j < 10; j++) acc[j] += c[j] * __half2float(up[j * 16]);
        }
        #pragma unroll
        for (int j = 0; j < 10; j++) spart[g * 160 + j * 16 + m] = acc[j];
        __syncthreads();

        if (t < 160) {
            float s = bias_r[t];
            #pragma unroll
            for (int g2 = 0; g2 < 36; g2++) s += spart[g2 * 160 + t];
            sfull[t] = s;
        }
        __syncthreads();
        if (t < 10) {
            float n2 = 0.f;
            #pragma unroll
            for (int mm = 0; mm < 16; mm++) { float v = sfull[t * 16 + mm]; n2 += v * v; }
            sscale[t] = (n2 / (1.f + n2)) / sqrtf(n2 + EPSF);
        }
        __syncthreads();
        if (t < 160) sv[t] = sfull[t] * sscale[t >> 4];
        __syncthreads();

        if (iter < 2) {                                   // agreement update
            for (int idx = t; idx < 11520; idx += 576) {
                int j = idx % 10;
                const __half2* up2 = (const __half2*)(ub + (size_t)idx * 16);
                const float* vj = sv + j * 16;
                float d = 0.f;
                #pragma unroll
                for (int q = 0; q < 8; q++) {
                    float2 a = __half22float2(up2[q]);
                    d += a.x * vj[2 * q] + a.y * vj[2 * q + 1];
                }
                if (iter == 0) sb[idx] = d; else sb[idx] += d;
            }
        }
        __syncthreads();
    }
    if (t < 10) {
        float n2 = 0.f;
        #pragma unroll
        for (int mm = 0; mm < 16; mm++) { float v = sv[t * 16 + mm]; n2 += v * v; }
        out[b * 10 + t] = sqrtf(n2 + EPSF);
    }
    if (t < 16) {
        float s = 0.f;
        const float* yb = y + b * 10;
        #pragma unroll
        for (int tt = 0; tt < 10; tt++) s += sv[t * 10 + tt] * yb[tt];
        g_masked[b * 16 + t] = s;
    }
}

// ---------------- FC GEMM ----------------
__global__ void gemm_kernel(const float* __restrict__ Wt, const float* __restrict__ bias,
                            float* __restrict__ out, int N, int K, int which) {
    __shared__ float As[16][16];
    __shared__ float Bs[16][17];
    const float* A; float* C;
    if (which == 0)      { A = g_masked; C = g_fc1; }
    else if (which == 1) { A = g_fc1;    C = g_fc2; }
    else                 { A = g_fc2;    C = out + 2560; }
    int tx = threadIdx.x, ty = threadIdx.y;
    int n0 = blockIdx.x * 16, m0 = blockIdx.y * 16;
    float acc = 0.f;
    for (int k0 = 0; k0 < K; k0 += 16) {
        As[ty][tx] = A[(size_t)(m0 + ty) * K + k0 + tx];
        Bs[ty][tx] = Wt[(size_t)(n0 + ty) * K + k0 + tx];
        __syncthreads();
        #pragma unroll
        for (int kk = 0; kk < 16; kk++) acc += As[ty][kk] * Bs[tx][kk];
        __syncthreads();
    }
    acc += bias[n0 + tx];
    if (which == 2) acc = 1.f / (1.f + expf(-acc));
    C[(size_t)(m0 + ty) * N + n0 + tx] = acc;
}

// ---------------- launch ----------------
extern "C" void kernel_launch(void* const* d_in, const int* in_sizes, int n_in,
                              void* d_out, int out_size) {
    (void)in_sizes; (void)n_in; (void)out_size;
    const float* x   = (const float*)d_in[0];
    const float* y   = (const float*)d_in[1];
    const float* c1w = (const float*)d_in[2];
    const float* c1b = (const float*)d_in[3];
    const float* c2w = (const float*)d_in[4];
    const float* c2b = (const float*)d_in[5];
    const float* W   = (const float*)d_in[6];
    const float* br  = (const float*)d_in[7];
    const float* f1w = (const float*)d_in[8];
    const float* f1b = (const float*)d_in[9];
    const float* f2w = (const float*)d_in[10];
    const float* f2b = (const float*)d_in[11];
    const float* f3w = (const float*)d_in[12];
    const float* f3b = (const float*)d_in[13];
    float* out = (float*)d_out;

    prep_w_kernel<<<dim3(81, 256), 256>>>(c2w);
    conv1_kernel<<<dim3(8, 256), 256>>>(x, c1w, c1b);
    caps1_mma_kernel<<<dim3(2, 72), 256, SMEM_C1>>>(c2b);
    u_kernel<<<dim3(256, 8), 256>>>(W);
    routing_kernel<<<256, 576>>>(y, br, out);
    gemm_kernel<<<dim3(32, 16), dim3(16, 16)>>>(f1w, f1b, out, 512, 16, 0);
    gemm_kernel<<<dim3(64, 16), dim3(16, 16)>>>(f2w, f2b, out, 1024, 512, 1);
    gemm_kernel<<<dim3(49, 16), dim3(16, 16)>>>(f3w, f3b, out, 784, 1024, 2);
}